// round 2
// baseline (speedup 1.0000x reference)
#include <cuda_runtime.h>
#include <cuda_fp16.h>
#include <math.h>
#include <stdint.h>

#define N_TOK 4096
#define DIMSZ 1024
#define NEXP  8
#define HID   4096
#define EPSV  1e-6f
#define MAX_BLK 40

// ---------------- scratch (static __device__: no allocations) ----------------
__device__ float  g_gateval[N_TOK];
__device__ int    g_expert[N_TOK];
__device__ float  g_weight[N_TOK];
__device__ float  g_denom[NEXP];
__device__ int    g_counts[NEXP];
__device__ int    g_cursor[NEXP];
__device__ int    g_perm[N_TOK];
__device__ __half g_xg[(size_t)N_TOK * DIMSZ];        // gathered x, fp16, sorted order
__device__ __half g_h[(size_t)N_TOK * HID];           // gelu(x@W1), fp16, sorted order
__device__ int    g_blk_expert[MAX_BLK];
__device__ int    g_blk_start[MAX_BLK];
__device__ int    g_blk_rows[MAX_BLK];
__device__ int    g_nblk;

__device__ __forceinline__ uint32_t s2u(const void* p) {
    return (uint32_t)__cvta_generic_to_shared(p);
}

// ---------------- kernel 0: reset ----------------
__global__ void init_kernel() {
    int t = threadIdx.x;
    if (t < NEXP) { g_denom[t] = 0.f; g_counts[t] = 0; }
}

// ---------------- kernel 1: gate (logits -> softmax -> top1 -> denom) --------
__global__ void gate_kernel(const float* __restrict__ x,
                            const float* __restrict__ wg,
                            const float* __restrict__ bg) {
    int warp = threadIdx.x >> 5, lane = threadIdx.x & 31;
    int t = blockIdx.x * 8 + warp;
    if (t >= N_TOK) return;
    const float* xr = x + (size_t)t * DIMSZ;
    float acc[NEXP];
#pragma unroll
    for (int e = 0; e < NEXP; e++) acc[e] = 0.f;
    for (int k = lane; k < DIMSZ; k += 32) {
        float xv = __ldg(xr + k);
        const float* wr = wg + (size_t)k * NEXP;
#pragma unroll
        for (int e = 0; e < NEXP; e++) acc[e] = fmaf(xv, __ldg(wr + e), acc[e]);
    }
#pragma unroll
    for (int e = 0; e < NEXP; e++)
#pragma unroll
        for (int o = 16; o > 0; o >>= 1)
            acc[e] += __shfl_xor_sync(0xFFFFFFFFu, acc[e], o);
    if (lane == 0) {
#pragma unroll
        for (int e = 0; e < NEXP; e++) acc[e] += bg[e];
        // argmax (first max wins, strict >)
        int top = 0; float best = acc[0];
#pragma unroll
        for (int e = 1; e < NEXP; e++) if (acc[e] > best) { best = acc[e]; top = e; }
        float m = best;                 // max logit
        float s = 0.f;
#pragma unroll
        for (int e = 0; e < NEXP; e++) s += expf(acc[e] - m);
        float gv = 1.0f / s;            // exp(best-m)=1
        g_gateval[t] = gv;
        g_expert[t]  = top;
        atomicAdd(&g_denom[top], gv);
        atomicAdd(&g_counts[top], 1);
    }
}

// ---------------- kernel 2: route (sort by expert, block list, weights) ------
__global__ void route_kernel() {
    int tid = threadIdx.x;
    if (tid == 0) {
        int acc = 0, nb = 0;
        for (int e = 0; e < NEXP; e++) {
            g_cursor[e] = acc;
            int c = g_counts[e];
            for (int s = 0; s < c; s += 128) {
                g_blk_expert[nb] = e;
                g_blk_start[nb]  = acc + s;
                g_blk_rows[nb]   = min(128, c - s);
                nb++;
            }
            acc += c;
        }
        g_nblk = nb;
    }
    __syncthreads();
    for (int t = tid; t < N_TOK; t += blockDim.x) {
        int e = g_expert[t];
        int pos = atomicAdd(&g_cursor[e], 1);
        g_perm[pos] = t;
        g_weight[t] = g_gateval[t] / (g_denom[e] + EPSV) * (float)N_TOK;
    }
}

// ---------------- kernel 3: gather x into fp16 (sorted order) ----------------
__global__ void gather_kernel(const float* __restrict__ x) {
    int i = blockIdx.x;
    int t = g_perm[i];
    const float4* src = (const float4*)(x + (size_t)t * DIMSZ);
    __half2* dst = (__half2*)(g_xg + (size_t)i * DIMSZ);
    for (int j = threadIdx.x; j < DIMSZ / 4; j += blockDim.x) {
        float4 v = src[j];
        dst[j * 2 + 0] = __floats2half2_rn(v.x, v.y);
        dst[j * 2 + 1] = __floats2half2_rn(v.z, v.w);
    }
}

// ---------------- grouped GEMM (fp16 mma.sync, 128x128x32 tiles) -------------
// PHASE 1: A=g_xg [*,KDIM], B=W1[e] -> gelu -> g_h (fp16)
// PHASE 2: A=g_h  [*,KDIM], B=W2[e] -> *weight -> scatter to out (fp32)
template <int KDIM, int NDIM, int PHASE>
__global__ void __launch_bounds__(256, 2) grouped_gemm(
    const float* __restrict__ Bglob,   // W [E, KDIM, NDIM] row-major
    const float* __restrict__ bias,    // [E, NDIM]
    float* __restrict__ out)           // used only in PHASE 2
{
    int blk = blockIdx.x;
    if (blk >= g_nblk) return;
    const int e    = g_blk_expert[blk];
    const int s    = g_blk_start[blk];
    const int rows = g_blk_rows[blk];
    const int n0   = blockIdx.y * 128;

    const __half* A = (PHASE == 1 ? g_xg : g_h) + (size_t)s * KDIM;
    const float*  B = Bglob + (size_t)e * KDIM * NDIM + n0;

    __shared__ __half As[2][128][40];    // [m][k] + pad (row 80B, 16B-mult)
    __shared__ __half Bs[2][32][136];    // [k][n] + pad (row 272B)

    const int tid  = threadIdx.x;
    const int warp = tid >> 5, lane = tid & 31;
    const int wm = warp >> 1;   // 0..3 -> m offset wm*32
    const int wn = warp & 1;    // 0..1 -> n offset wn*64

    float acc[2][8][4];
#pragma unroll
    for (int a = 0; a < 2; a++)
#pragma unroll
        for (int b = 0; b < 8; b++)
#pragma unroll
            for (int c = 0; c < 4; c++) acc[a][b][c] = 0.f;

    auto loadA = [&](int st, int k0) {
#pragma unroll
        for (int it = 0; it < 2; it++) {
            int id = tid + it * 256;           // 512 chunks = 128 rows * 4
            int r = id >> 2, c = (id & 3) * 8; // 8 halves per chunk
            uint4 v = make_uint4(0u, 0u, 0u, 0u);
            if (s + r < N_TOK)
                v = *(const uint4*)(A + (size_t)r * KDIM + k0 + c);
            *(uint4*)&As[st][r][c] = v;
        }
    };
    auto loadB = [&](int st, int k0) {
#pragma unroll
        for (int it = 0; it < 4; it++) {
            int id = tid + it * 256;            // 1024 float4 = 32 rows * 32
            int r = id >> 5, c4 = id & 31;
            float4 v = *(const float4*)(B + (size_t)(k0 + r) * NDIM + c4 * 4);
            *(__half2*)&Bs[st][r][c4 * 4 + 0] = __floats2half2_rn(v.x, v.y);
            *(__half2*)&Bs[st][r][c4 * 4 + 2] = __floats2half2_rn(v.z, v.w);
        }
    };

    loadA(0, 0);
    loadB(0, 0);
    __syncthreads();

    const int nk = KDIM / 32;
    for (int kc = 0; kc < nk; kc++) {
        int cur = kc & 1, nxt = cur ^ 1;
        if (kc + 1 < nk) { loadA(nxt, (kc + 1) * 32); loadB(nxt, (kc + 1) * 32); }

#pragma unroll
        for (int ks = 0; ks < 2; ks++) {
            const int kk = ks * 16;
            // A fragments: two m16 tiles per warp
            uint32_t afr[2][4];
#pragma unroll
            for (int mt = 0; mt < 2; mt++) {
                int mbase = wm * 32 + mt * 16;
                int r = mbase + (lane & 7) + ((lane >> 3) & 1) * 8;
                int c = kk + (lane >> 4) * 8;
                uint32_t addr = s2u(&As[cur][r][c]);
                asm volatile("ldmatrix.sync.aligned.m8n8.x4.shared.b16 {%0,%1,%2,%3}, [%4];\n"
                             : "=r"(afr[mt][0]), "=r"(afr[mt][1]),
                               "=r"(afr[mt][2]), "=r"(afr[mt][3])
                             : "r"(addr));
            }
            // B fragments: eight n8 tiles per warp (4x ldmatrix.trans.x4)
            uint32_t bfr[8][2];
#pragma unroll
            for (int q = 0; q < 4; q++) {
                int nbase = wn * 64 + q * 16;
                int mi = lane >> 3;
                int kr = kk + (mi & 1) * 8 + (lane & 7);
                int nc = nbase + (mi >> 1) * 8;
                uint32_t addr = s2u(&Bs[cur][kr][nc]);
                uint32_t r0, r1, r2, r3;
                asm volatile("ldmatrix.sync.aligned.m8n8.x4.trans.shared.b16 {%0,%1,%2,%3}, [%4];\n"
                             : "=r"(r0), "=r"(r1), "=r"(r2), "=r"(r3)
                             : "r"(addr));
                bfr[q * 2 + 0][0] = r0; bfr[q * 2 + 0][1] = r1;
                bfr[q * 2 + 1][0] = r2; bfr[q * 2 + 1][1] = r3;
            }
#pragma unroll
            for (int mt = 0; mt < 2; mt++)
#pragma unroll
                for (int nf = 0; nf < 8; nf++) {
                    asm volatile(
                        "mma.sync.aligned.m16n8k16.row.col.f32.f16.f16.f32 "
                        "{%0,%1,%2,%3}, {%4,%5,%6,%7}, {%8,%9}, {%0,%1,%2,%3};\n"
                        : "+f"(acc[mt][nf][0]), "+f"(acc[mt][nf][1]),
                          "+f"(acc[mt][nf][2]), "+f"(acc[mt][nf][3])
                        : "r"(afr[mt][0]), "r"(afr[mt][1]),
                          "r"(afr[mt][2]), "r"(afr[mt][3]),
                          "r"(bfr[nf][0]), "r"(bfr[nf][1]));
                }
        }
        __syncthreads();
    }

    // ---------------- epilogue ----------------
#pragma unroll
    for (int mt = 0; mt < 2; mt++) {
#pragma unroll
        for (int nf = 0; nf < 8; nf++) {
            int n = wn * 64 + nf * 8 + (lane & 3) * 2;
#pragma unroll
            for (int hrow = 0; hrow < 2; hrow++) {
                int mm = wm * 32 + mt * 16 + (lane >> 2) + hrow * 8;
                if (mm < rows) {
                    float v0 = acc[mt][nf][hrow * 2 + 0] + bias[(size_t)e * NDIM + n0 + n];
                    float v1 = acc[mt][nf][hrow * 2 + 1] + bias[(size_t)e * NDIM + n0 + n + 1];
                    if (PHASE == 1) {
                        float g0 = 0.5f * v0 * (1.f + erff(v0 * 0.70710678118654752f));
                        float g1 = 0.5f * v1 * (1.f + erff(v1 * 0.70710678118654752f));
                        *(__half2*)&g_h[(size_t)(s + mm) * HID + n0 + n] =
                            __floats2half2_rn(g0, g1);
                    } else {
                        int t = g_perm[s + mm];
                        float w = g_weight[t];
                        float2 o; o.x = w * v0; o.y = w * v1;
                        *(float2*)&out[(size_t)t * DIMSZ + n0 + n] = o;
                    }
                }
            }
        }
    }
}

// ---------------- launch ----------------
extern "C" void kernel_launch(void* const* d_in, const int* in_sizes, int n_in,
                              void* d_out, int out_size) {
    (void)in_sizes; (void)n_in; (void)out_size;
    const float* x  = (const float*)d_in[0];
    const float* wg = (const float*)d_in[1];
    const float* bg = (const float*)d_in[2];
    const float* W1 = (const float*)d_in[3];
    const float* b1 = (const float*)d_in[4];
    const float* W2 = (const float*)d_in[5];
    const float* b2 = (const float*)d_in[6];
    float* out = (float*)d_out;

    init_kernel<<<1, 32>>>();
    gate_kernel<<<N_TOK / 8, 256>>>(x, wg, bg);
    route_kernel<<<1, 256>>>();
    gather_kernel<<<N_TOK, 128>>>(x);
    grouped_gemm<DIMSZ, HID, 1><<<dim3(MAX_BLK, HID / 128), 256>>>(W1, b1, nullptr);
    grouped_gemm<HID, DIMSZ, 2><<<dim3(MAX_BLK, DIMSZ / 128), 256>>>(W2, b2, out);
}